// round 1
// baseline (speedup 1.0000x reference)
#include <cuda_runtime.h>
#include <math.h>

// Problem constants (ManifoldGPRFilter: N=100000, D=64, E=1000000, L=10)
#define NMAX 100000
#define EMAX 1000000
#define DIM  64
#define EPSV 1e-8f

// ---------------- static device scratch (no runtime allocation) ----------------
__device__ float g_H0[(size_t)NMAX * DIM];
__device__ float g_H1[(size_t)NMAX * DIM];
__device__ int   g_deg[NMAX];
__device__ int   g_off[NMAX + 1];
__device__ int   g_cur[NMAX];
__device__ int   g_srcs[EMAX];
__device__ float g_vals[EMAX];
__device__ int   g_bsum[1024];

// ---------------- CSR build ----------------
__global__ void k_zero_deg(int n) {
    int i = blockIdx.x * blockDim.x + threadIdx.x;
    if (i < n) g_deg[i] = 0;
}

__global__ void k_hist(const int* __restrict__ dst, int e) {
    int i = blockIdx.x * blockDim.x + threadIdx.x;
    if (i < e) atomicAdd(&g_deg[dst[i]], 1);
}

#define SCAN_B 1024
__global__ void k_scan1(int n) {
    __shared__ int sh[SCAN_B];
    int i = blockIdx.x * SCAN_B + threadIdx.x;
    int v = (i < n) ? g_deg[i] : 0;
    sh[threadIdx.x] = v;
    __syncthreads();
    for (int o = 1; o < SCAN_B; o <<= 1) {
        int t = 0;
        if (threadIdx.x >= o) t = sh[threadIdx.x - o];
        __syncthreads();
        if (threadIdx.x >= o) sh[threadIdx.x] += t;
        __syncthreads();
    }
    if (i < n) g_off[i] = sh[threadIdx.x] - v;        // exclusive within block
    if (threadIdx.x == SCAN_B - 1) g_bsum[blockIdx.x] = sh[threadIdx.x];
}

__global__ void k_scan2(int nb, int n) {
    __shared__ int sh[1024];
    int v = (threadIdx.x < nb) ? g_bsum[threadIdx.x] : 0;
    sh[threadIdx.x] = v;
    __syncthreads();
    for (int o = 1; o < 1024; o <<= 1) {
        int t = 0;
        if (threadIdx.x >= o) t = sh[threadIdx.x - o];
        __syncthreads();
        if (threadIdx.x >= o) sh[threadIdx.x] += t;
        __syncthreads();
    }
    if (threadIdx.x < nb) g_bsum[threadIdx.x] = sh[threadIdx.x] - v;  // exclusive
    if (threadIdx.x == 1023) g_off[n] = sh[1023];                     // total = E
}

__global__ void k_scan3(int n) {
    int i = blockIdx.x * SCAN_B + threadIdx.x;
    if (i < n) {
        g_off[i] += g_bsum[blockIdx.x];
        g_cur[i] = g_off[i];
    }
}

__global__ void k_scatter(const int* __restrict__ src, const int* __restrict__ dst,
                          const float* __restrict__ val, int e) {
    int i = blockIdx.x * blockDim.x + threadIdx.x;
    if (i < e) {
        int d = dst[i];
        int pos = atomicAdd(&g_cur[d], 1);
        g_srcs[pos] = src[i];
        g_vals[pos] = val[i];
    }
}

// ---------------- Z init: Z = w[0] * X ----------------
__global__ void k_initZ(const float* __restrict__ X, float* __restrict__ Z,
                        const float* __restrict__ w, int n4) {
    int i = blockIdx.x * blockDim.x + threadIdx.x;
    if (i < n4) {
        float w0 = __ldg(w);
        float4 x = ((const float4*)X)[i];
        float4 z;
        z.x = w0 * x.x; z.y = w0 * x.y; z.z = w0 * x.z; z.w = w0 * x.w;
        ((float4*)Z)[i] = z;
    }
}

// ---------------- fused SpMM + hyperbolic renorm + Z accumulation ----------------
// One warp per destination row. Each lane owns columns lane and lane+32.
__global__ __launch_bounds__(256)
void k_spmm_renorm(const float* __restrict__ Hin, float* __restrict__ Hout,
                   float* __restrict__ Z, const float* __restrict__ w,
                   int l, int n) {
    int warp = (blockIdx.x * blockDim.x + threadIdx.x) >> 5;
    int lane = threadIdx.x & 31;
    if (warp >= n) return;

    int beg = g_off[warp];
    int end = g_off[warp + 1];

    float a0 = 0.f, a1 = 0.f;
    for (int e = beg; e < end; e++) {
        int   s = g_srcs[e];
        float v = g_vals[e];
        const float* hp = Hin + (size_t)s * DIM;
        a0 += v * __ldg(hp + lane);
        a1 += v * __ldg(hp + lane + 32);
    }

    // row norm via warp reduction
    float ss = a0 * a0 + a1 * a1;
    #pragma unroll
    for (int o = 16; o; o >>= 1) ss += __shfl_xor_sync(0xffffffffu, ss, o);

    float nrm   = sqrtf(ss) + EPSV;
    float scale = tanhf(nrm) / nrm;
    float wl    = __ldg(w + l);

    float h0 = a0 * scale;
    float h1 = a1 * scale;

    size_t base = (size_t)warp * DIM + lane;
    Hout[base]      = h0;
    Hout[base + 32] = h1;
    Z[base]      += wl * h0;
    Z[base + 32] += wl * h1;
}

// ---------------- launch ----------------
extern "C" void kernel_launch(void* const* d_in, const int* in_sizes, int n_in,
                              void* d_out, int out_size) {
    const float* X    = (const float*)d_in[0];
    const float* vals = (const float*)d_in[1];
    const float* w    = (const float*)d_in[2];
    const int*   src  = (const int*)d_in[3];
    const int*   dst  = (const int*)d_in[4];
    float* Z = (float*)d_out;

    int n = in_sizes[0] / DIM;
    int e = in_sizes[1];
    int L = in_sizes[2] - 1;

    float* h0; float* h1;
    cudaGetSymbolAddress((void**)&h0, g_H0);
    cudaGetSymbolAddress((void**)&h1, g_H1);

    // ---- CSR build (by destination) ----
    int nb = (n + SCAN_B - 1) / SCAN_B;
    k_zero_deg<<<(n + 255) / 256, 256>>>(n);
    k_hist<<<(e + 255) / 256, 256>>>(dst, e);
    k_scan1<<<nb, SCAN_B>>>(n);
    k_scan2<<<1, 1024>>>(nb, n);
    k_scan3<<<nb, SCAN_B>>>(n);
    k_scatter<<<(e + 255) / 256, 256>>>(src, dst, vals, e);

    // ---- Z = w0 * X ----
    int n4 = n * DIM / 4;
    k_initZ<<<(n4 + 255) / 256, 256>>>(X, Z, w, n4);

    // ---- L propagation steps (ping-pong H buffers) ----
    int blocks = (n * 32 + 255) / 256;
    for (int l = 1; l <= L; l++) {
        const float* Hin = (l == 1) ? X : ((l & 1) ? h1 : h0);
        float* Hout      = ((l & 1) ? h0 : h1);
        k_spmm_renorm<<<blocks, 256>>>(Hin, Hout, Z, w, l, n);
    }
}

// round 2
// speedup vs baseline: 1.1607x; 1.1607x over previous
#include <cuda_runtime.h>
#include <cuda_fp16.h>
#include <math.h>

// Problem constants (ManifoldGPRFilter: N=100000, D=64, E=1000000, L=10)
#define NMAX 100000
#define EMAX 1000000
#define DIM  64
#define EPSV 1e-8f

// ---------------- static device scratch (no runtime allocation) ----------------
__device__ __half2 g_Xh[(size_t)NMAX * (DIM / 2)];
__device__ __half2 g_H0[(size_t)NMAX * (DIM / 2)];
__device__ __half2 g_H1[(size_t)NMAX * (DIM / 2)];
__device__ int   g_deg[NMAX];
__device__ int   g_off[NMAX + 1];
__device__ int   g_cur[NMAX];
__device__ int   g_srcs[EMAX];
__device__ float g_vals[EMAX];
__device__ int   g_bsum[1024];

// ---------------- CSR build ----------------
__global__ void k_zero_deg(int n) {
    int i = blockIdx.x * blockDim.x + threadIdx.x;
    if (i < n) g_deg[i] = 0;
}

__global__ void k_hist(const int* __restrict__ dst, int e) {
    int i = blockIdx.x * blockDim.x + threadIdx.x;
    if (i < e) atomicAdd(&g_deg[dst[i]], 1);
}

#define SCAN_B 1024
__global__ void k_scan1(int n) {
    __shared__ int sh[SCAN_B];
    int i = blockIdx.x * SCAN_B + threadIdx.x;
    int v = (i < n) ? g_deg[i] : 0;
    sh[threadIdx.x] = v;
    __syncthreads();
    for (int o = 1; o < SCAN_B; o <<= 1) {
        int t = 0;
        if (threadIdx.x >= o) t = sh[threadIdx.x - o];
        __syncthreads();
        if (threadIdx.x >= o) sh[threadIdx.x] += t;
        __syncthreads();
    }
    if (i < n) g_off[i] = sh[threadIdx.x] - v;        // exclusive within block
    if (threadIdx.x == SCAN_B - 1) g_bsum[blockIdx.x] = sh[threadIdx.x];
}

__global__ void k_scan2(int nb, int n) {
    __shared__ int sh[1024];
    int v = (threadIdx.x < nb) ? g_bsum[threadIdx.x] : 0;
    sh[threadIdx.x] = v;
    __syncthreads();
    for (int o = 1; o < 1024; o <<= 1) {
        int t = 0;
        if (threadIdx.x >= o) t = sh[threadIdx.x - o];
        __syncthreads();
        if (threadIdx.x >= o) sh[threadIdx.x] += t;
        __syncthreads();
    }
    if (threadIdx.x < nb) g_bsum[threadIdx.x] = sh[threadIdx.x] - v;  // exclusive
    if (threadIdx.x == 1023) g_off[n] = sh[1023];                     // total = E
}

__global__ void k_scan3(int n) {
    int i = blockIdx.x * SCAN_B + threadIdx.x;
    if (i < n) {
        g_off[i] += g_bsum[blockIdx.x];
        g_cur[i] = g_off[i];
    }
}

__global__ void k_scatter(const int* __restrict__ src, const int* __restrict__ dst,
                          const float* __restrict__ val, int e) {
    int i = blockIdx.x * blockDim.x + threadIdx.x;
    if (i < e) {
        int d = dst[i];
        int pos = atomicAdd(&g_cur[d], 1);
        g_srcs[pos] = src[i];
        g_vals[pos] = val[i];
    }
}

// ---------------- Z = w0 * X  and  Xh = half(X), fused ----------------
// Each thread handles 4 floats (one float4 of X).
__global__ void k_initZ_conv(const float* __restrict__ X, float* __restrict__ Z,
                             __half2* __restrict__ Xh,
                             const float* __restrict__ w, int n4) {
    int i = blockIdx.x * blockDim.x + threadIdx.x;
    if (i < n4) {
        float w0 = __ldg(w);
        float4 x = ((const float4*)X)[i];
        float4 z;
        z.x = w0 * x.x; z.y = w0 * x.y; z.z = w0 * x.z; z.w = w0 * x.w;
        ((float4*)Z)[i] = z;
        Xh[i * 2]     = __floats2half2_rn(x.x, x.y);
        Xh[i * 2 + 1] = __floats2half2_rn(x.z, x.w);
    }
}

// ---------------- fused SpMM + hyperbolic renorm + Z accumulation ----------------
// One warp per destination row. Lane owns columns (2*lane, 2*lane+1) as one half2.
// Gather = ONE 128B line per edge.
__global__ __launch_bounds__(256)
void k_spmm_renorm(const __half2* __restrict__ Hin, __half2* __restrict__ Hout,
                   float* __restrict__ Z, const float* __restrict__ w,
                   int l, int n, int writeH) {
    int warp = (blockIdx.x * blockDim.x + threadIdx.x) >> 5;
    int lane = threadIdx.x & 31;
    if (warp >= n) return;

    int beg = g_off[warp];
    int end = g_off[warp + 1];

    float a0 = 0.f, a1 = 0.f;
    int e = beg;
    // 2x unrolled main loop for MLP
    for (; e + 2 <= end; e += 2) {
        int   s0 = g_srcs[e];
        int   s1 = g_srcs[e + 1];
        float v0 = g_vals[e];
        float v1 = g_vals[e + 1];
        float2 h0 = __half22float2(__ldg(Hin + (size_t)s0 * 32 + lane));
        float2 h1 = __half22float2(__ldg(Hin + (size_t)s1 * 32 + lane));
        a0 += v0 * h0.x + v1 * h1.x;
        a1 += v0 * h0.y + v1 * h1.y;
    }
    if (e < end) {
        int   s = g_srcs[e];
        float v = g_vals[e];
        float2 h = __half22float2(__ldg(Hin + (size_t)s * 32 + lane));
        a0 += v * h.x;
        a1 += v * h.y;
    }

    // row norm via warp reduction
    float ss = a0 * a0 + a1 * a1;
    #pragma unroll
    for (int o = 16; o; o >>= 1) ss += __shfl_xor_sync(0xffffffffu, ss, o);

    float nrm   = sqrtf(ss) + EPSV;
    float scale = tanhf(nrm) / nrm;
    float wl    = __ldg(w + l);

    float h0 = a0 * scale;
    float h1 = a1 * scale;

    if (writeH)
        Hout[(size_t)warp * 32 + lane] = __floats2half2_rn(h0, h1);

    float2* zp = reinterpret_cast<float2*>(Z + (size_t)warp * DIM) + lane;
    float2 z = *zp;
    z.x += wl * h0;
    z.y += wl * h1;
    *zp = z;
}

// ---------------- launch ----------------
extern "C" void kernel_launch(void* const* d_in, const int* in_sizes, int n_in,
                              void* d_out, int out_size) {
    const float* X    = (const float*)d_in[0];
    const float* vals = (const float*)d_in[1];
    const float* w    = (const float*)d_in[2];
    const int*   src  = (const int*)d_in[3];
    const int*   dst  = (const int*)d_in[4];
    float* Z = (float*)d_out;

    int n = in_sizes[0] / DIM;
    int e = in_sizes[1];
    int L = in_sizes[2] - 1;

    __half2* xh; __half2* h0; __half2* h1;
    cudaGetSymbolAddress((void**)&xh, g_Xh);
    cudaGetSymbolAddress((void**)&h0, g_H0);
    cudaGetSymbolAddress((void**)&h1, g_H1);

    // ---- CSR build (by destination) ----
    int nb = (n + SCAN_B - 1) / SCAN_B;
    k_zero_deg<<<(n + 255) / 256, 256>>>(n);
    k_hist<<<(e + 255) / 256, 256>>>(dst, e);
    k_scan1<<<nb, SCAN_B>>>(n);
    k_scan2<<<1, 1024>>>(nb, n);
    k_scan3<<<nb, SCAN_B>>>(n);
    k_scatter<<<(e + 255) / 256, 256>>>(src, dst, vals, e);

    // ---- Z = w0 * X, Xh = half(X) ----
    int n4 = n * DIM / 4;
    k_initZ_conv<<<(n4 + 255) / 256, 256>>>(X, Z, xh, w, n4);

    // ---- L propagation steps (ping-pong fp16 H buffers) ----
    int blocks = (n * 32 + 255) / 256;
    for (int l = 1; l <= L; l++) {
        const __half2* Hin = (l == 1) ? xh : ((l & 1) ? h1 : h0);
        __half2* Hout      = ((l & 1) ? h0 : h1);
        int writeH = (l < L) ? 1 : 0;
        k_spmm_renorm<<<blocks, 256>>>(Hin, Hout, Z, w, l, n, writeH);
    }
}

// round 3
// speedup vs baseline: 1.2723x; 1.0961x over previous
#include <cuda_runtime.h>
#include <cuda_fp16.h>
#include <math.h>

// Problem constants (ManifoldGPRFilter: N=100000, D=64, E=1000000, L=10)
#define NMAX 100000
#define EMAX 1000000
#define DIM  64
#define EPSV 1e-8f

// ---------------- static device scratch (no runtime allocation) ----------------
__device__ __half2 g_Xh[(size_t)NMAX * (DIM / 2)];
__device__ __half2 g_H0[(size_t)NMAX * (DIM / 2)];
__device__ __half2 g_H1[(size_t)NMAX * (DIM / 2)];
__device__ int   g_deg[NMAX];
__device__ int   g_off[NMAX + 1];
__device__ int   g_cur[NMAX];
__device__ int2  g_edge[EMAX];     // packed (src, float-bits of val)
__device__ int   g_bsum[1024];

// ---------------- CSR build ----------------
__global__ void k_zero_deg(int n) {
    int i = blockIdx.x * blockDim.x + threadIdx.x;
    if (i < n) g_deg[i] = 0;
}

__global__ void k_hist(const int* __restrict__ dst, int e) {
    int i = blockIdx.x * blockDim.x + threadIdx.x;
    if (i < e) atomicAdd(&g_deg[dst[i]], 1);
}

#define SCAN_B 1024
__global__ void k_scan1(int n) {
    __shared__ int sh[SCAN_B];
    int i = blockIdx.x * SCAN_B + threadIdx.x;
    int v = (i < n) ? g_deg[i] : 0;
    sh[threadIdx.x] = v;
    __syncthreads();
    for (int o = 1; o < SCAN_B; o <<= 1) {
        int t = 0;
        if (threadIdx.x >= o) t = sh[threadIdx.x - o];
        __syncthreads();
        if (threadIdx.x >= o) sh[threadIdx.x] += t;
        __syncthreads();
    }
    if (i < n) g_off[i] = sh[threadIdx.x] - v;        // exclusive within block
    if (threadIdx.x == SCAN_B - 1) g_bsum[blockIdx.x] = sh[threadIdx.x];
}

// 128-thread block-level scan of the (<=98) block sums
__global__ void k_scan2(int nb, int n) {
    __shared__ int sh[128];
    int v = (threadIdx.x < nb) ? g_bsum[threadIdx.x] : 0;
    sh[threadIdx.x] = v;
    __syncthreads();
    for (int o = 1; o < 128; o <<= 1) {
        int t = 0;
        if (threadIdx.x >= o) t = sh[threadIdx.x - o];
        __syncthreads();
        if (threadIdx.x >= o) sh[threadIdx.x] += t;
        __syncthreads();
    }
    if (threadIdx.x < nb) g_bsum[threadIdx.x] = sh[threadIdx.x] - v;  // exclusive
    if (threadIdx.x == 127) g_off[n] = sh[127];                       // total = E
}

__global__ void k_scan3(int n) {
    int i = blockIdx.x * SCAN_B + threadIdx.x;
    if (i < n) {
        g_off[i] += g_bsum[blockIdx.x];
        g_cur[i] = g_off[i];
    }
}

__global__ void k_scatter(const int* __restrict__ src, const int* __restrict__ dst,
                          const float* __restrict__ val, int e) {
    int i = blockIdx.x * blockDim.x + threadIdx.x;
    if (i < e) {
        int d = dst[i];
        int pos = atomicAdd(&g_cur[d], 1);
        g_edge[pos] = make_int2(src[i], __float_as_int(val[i]));
    }
}

// ---------------- Z = w0 * X  and  Xh = half(X), fused ----------------
__global__ void k_initZ_conv(const float* __restrict__ X, float* __restrict__ Z,
                             __half2* __restrict__ Xh,
                             const float* __restrict__ w, int n4) {
    int i = blockIdx.x * blockDim.x + threadIdx.x;
    if (i < n4) {
        float w0 = __ldg(w);
        float4 x = ((const float4*)X)[i];
        float4 z;
        z.x = w0 * x.x; z.y = w0 * x.y; z.z = w0 * x.z; z.w = w0 * x.w;
        ((float4*)Z)[i] = z;
        Xh[i * 2]     = __floats2half2_rn(x.x, x.y);
        Xh[i * 2 + 1] = __floats2half2_rn(x.z, x.w);
    }
}

// ---------------- fused SpMM + hyperbolic renorm + Z accumulation ----------------
// One warp per destination row, processing edges in PAIRS:
//   lanes 0-15  gather edge e   's 128B row (uint2 = 4 halves per lane)
//   lanes 16-31 gather edge e+1 's row
// => one LDG.64 covers two edges' gathers, one LDG.64 covers both edges' (src,val).
__global__ __launch_bounds__(256)
void k_spmm_renorm(const __half2* __restrict__ Hin, __half2* __restrict__ Hout,
                   float* __restrict__ Z, const float* __restrict__ w,
                   int l, int n, int writeH) {
    int warp = (blockIdx.x * blockDim.x + threadIdx.x) >> 5;
    int lane = threadIdx.x & 31;
    if (warp >= n) return;

    int half = lane >> 4;      // parity group
    int sub  = lane & 15;      // column group: owns cols [4*sub, 4*sub+4)

    int beg = g_off[warp];
    int end = g_off[warp + 1];

    const uint2* Hrows = reinterpret_cast<const uint2*>(Hin);

    float4 acc = make_float4(0.f, 0.f, 0.f, 0.f);

    int e = beg;
    // 4 edges per iteration: two independent (edge-pair) chains in flight
    for (; e + 4 <= end; e += 4) {
        int2 ed0 = __ldg(&g_edge[e + half]);
        int2 ed1 = __ldg(&g_edge[e + 2 + half]);
        uint2 h0 = __ldg(Hrows + (size_t)ed0.x * 16 + sub);
        uint2 h1 = __ldg(Hrows + (size_t)ed1.x * 16 + sub);
        float v0 = __int_as_float(ed0.y);
        float v1 = __int_as_float(ed1.y);
        float2 a01 = __half22float2(*(const __half2*)&h0.x);
        float2 a23 = __half22float2(*(const __half2*)&h0.y);
        float2 b01 = __half22float2(*(const __half2*)&h1.x);
        float2 b23 = __half22float2(*(const __half2*)&h1.y);
        acc.x += v0 * a01.x + v1 * b01.x;
        acc.y += v0 * a01.y + v1 * b01.y;
        acc.z += v0 * a23.x + v1 * b23.x;
        acc.w += v0 * a23.y + v1 * b23.y;
    }
    // remaining pair
    if (e + 2 <= end) {
        int2 ed = __ldg(&g_edge[e + half]);
        uint2 h = __ldg(Hrows + (size_t)ed.x * 16 + sub);
        float v = __int_as_float(ed.y);
        float2 a01 = __half22float2(*(const __half2*)&h.x);
        float2 a23 = __half22float2(*(const __half2*)&h.y);
        acc.x += v * a01.x;
        acc.y += v * a01.y;
        acc.z += v * a23.x;
        acc.w += v * a23.y;
        e += 2;
    }
    // odd tail: only parity-0 lanes process
    if (e < end && half == 0) {
        int2 ed = __ldg(&g_edge[e]);
        uint2 h = __ldg(Hrows + (size_t)ed.x * 16 + sub);
        float v = __int_as_float(ed.y);
        float2 a01 = __half22float2(*(const __half2*)&h.x);
        float2 a23 = __half22float2(*(const __half2*)&h.y);
        acc.x += v * a01.x;
        acc.y += v * a01.y;
        acc.z += v * a23.x;
        acc.w += v * a23.y;
    }

    // merge parity halves: lane s += lane s+16
    acc.x += __shfl_down_sync(0xffffffffu, acc.x, 16);
    acc.y += __shfl_down_sync(0xffffffffu, acc.y, 16);
    acc.z += __shfl_down_sync(0xffffffffu, acc.z, 16);
    acc.w += __shfl_down_sync(0xffffffffu, acc.w, 16);

    // row norm: reduce within lanes 0-15 (valid there)
    float ss = acc.x * acc.x + acc.y * acc.y + acc.z * acc.z + acc.w * acc.w;
    #pragma unroll
    for (int o = 8; o; o >>= 1) ss += __shfl_xor_sync(0xffffffffu, ss, o);

    if (half == 0) {
        float nrm   = sqrtf(ss) + EPSV;
        float scale = tanhf(nrm) / nrm;
        float wl    = __ldg(w + l);

        float h0 = acc.x * scale;
        float h1 = acc.y * scale;
        float h2 = acc.z * scale;
        float h3 = acc.w * scale;

        if (writeH) {
            uint2 hv;
            __half2 p01 = __floats2half2_rn(h0, h1);
            __half2 p23 = __floats2half2_rn(h2, h3);
            hv.x = *(const unsigned*)&p01;
            hv.y = *(const unsigned*)&p23;
            reinterpret_cast<uint2*>(Hout)[(size_t)warp * 16 + sub] = hv;
        }

        float4* zp = reinterpret_cast<float4*>(Z + (size_t)warp * DIM) + sub;
        float4 z = *zp;
        z.x += wl * h0;
        z.y += wl * h1;
        z.z += wl * h2;
        z.w += wl * h3;
        *zp = z;
    }
}

// ---------------- launch ----------------
extern "C" void kernel_launch(void* const* d_in, const int* in_sizes, int n_in,
                              void* d_out, int out_size) {
    const float* X    = (const float*)d_in[0];
    const float* vals = (const float*)d_in[1];
    const float* w    = (const float*)d_in[2];
    const int*   src  = (const int*)d_in[3];
    const int*   dst  = (const int*)d_in[4];
    float* Z = (float*)d_out;

    int n = in_sizes[0] / DIM;
    int e = in_sizes[1];
    int L = in_sizes[2] - 1;

    __half2* xh; __half2* h0; __half2* h1;
    cudaGetSymbolAddress((void**)&xh, g_Xh);
    cudaGetSymbolAddress((void**)&h0, g_H0);
    cudaGetSymbolAddress((void**)&h1, g_H1);

    // ---- CSR build (by destination) ----
    int nb = (n + SCAN_B - 1) / SCAN_B;
    k_zero_deg<<<(n + 255) / 256, 256>>>(n);
    k_hist<<<(e + 255) / 256, 256>>>(dst, e);
    k_scan1<<<nb, SCAN_B>>>(n);
    k_scan2<<<1, 128>>>(nb, n);
    k_scan3<<<nb, SCAN_B>>>(n);
    k_scatter<<<(e + 255) / 256, 256>>>(src, dst, vals, e);

    // ---- Z = w0 * X, Xh = half(X) ----
    int n4 = n * DIM / 4;
    k_initZ_conv<<<(n4 + 255) / 256, 256>>>(X, Z, xh, w, n4);

    // ---- L propagation steps (ping-pong fp16 H buffers) ----
    int blocks = (n * 32 + 255) / 256;
    for (int l = 1; l <= L; l++) {
        const __half2* Hin = (l == 1) ? xh : ((l & 1) ? h1 : h0);
        __half2* Hout      = ((l & 1) ? h0 : h1);
        int writeH = (l < L) ? 1 : 0;
        k_spmm_renorm<<<blocks, 256>>>(Hin, Hout, Z, w, l, n, writeH);
    }
}